// round 16
// baseline (speedup 1.0000x reference)
#include <cuda_runtime.h>
#include <cuda_bf16.h>

// OpticalSurface_33294586478821 — ray/sphere intersect + Snell refraction.
// Streaming HBM-bound: 24N B read, 28N B write. 4 rays/thread so all [N,3]
// traffic is aligned float4 (3x LDG.128 per input array per thread).

#define RSPH   50.0f        // sphere radius; center at (RSPH,0,0) local
#define INV_R  (1.0f/50.0f)
#define APR2   400.0f       // (DIAM/2)^2 = 20^2
#define ETA    (1.0f/1.5f)  // N1/N2

__device__ __forceinline__ void trace_one(
    float px, float py, float pz,
    float vx, float vy, float vz,
    float tx, float ty, float tz,
    float& ox, float& oy, float& oz,
    float& Tx, float& Ty, float& Tz,
    float& vld)
{
    // global -> local (SCALE = 1)
    float plx = px - tx, ply = py - ty, plz = pz - tz;

    // ray/sphere
    float ocx = plx - RSPH, ocy = ply, ocz = plz;
    float b    = ocx * vx + ocy * vy + ocz * vz;
    float c    = ocx * ocx + ocy * ocy + ocz * ocz - RSPH * RSPH;
    float disc = b * b - c;
    float sq   = sqrtf(fmaxf(disc, 0.0f));
    float t    = -b - sq;

    float qx = plx + t * vx, qy = ply + t * vy, qz = plz + t * vz;
    float r2 = qy * qy + qz * qz;
    bool valid = (disc >= 0.0f) && (t > 0.0f) && (r2 <= APR2);

    // normal, oriented against incoming ray
    float nx = (qx - RSPH) * INV_R;
    float ny = qy * INV_R;
    float nz = qz * INV_R;
    float vdn = vx * nx + vy * ny + vz * nz;
    if (vdn > 0.0f) { nx = -nx; ny = -ny; nz = -nz; }
    if (!valid)     { nx = -1.0f; ny = 0.0f; nz = 0.0f; }

    // global collision point (blocked rays keep P)
    ox = valid ? (qx + tx) : px;
    oy = valid ? (qy + ty) : py;
    oz = valid ? (qz + tz) : pz;

    // vector Snell, clamped past critical angle
    float cos_i = -(vx * nx + vy * ny + vz * nz);
    float k = fmaxf(1.0f - ETA * ETA * (1.0f - cos_i * cos_i), 0.0f);
    float f = ETA * cos_i - sqrtf(k);
    float ux = ETA * vx + f * nx;
    float uy = ETA * vy + f * ny;
    float uz = ETA * vz + f * nz;
    float inv = rsqrtf(ux * ux + uy * uy + uz * uz);
    Tx = ux * inv; Ty = uy * inv; Tz = uz * inv;

    vld = valid ? 1.0f : 0.0f;
}

__global__ __launch_bounds__(256)
void optical_quad_kernel(const float4* __restrict__ P4,
                         const float4* __restrict__ V4,
                         const float*  __restrict__ toff,
                         float4* __restrict__ pt4,
                         float4* __restrict__ T4,
                         float4* __restrict__ vld4,
                         int nq)
{
    int i = blockIdx.x * blockDim.x + threadIdx.x;
    if (i >= nq) return;

    const float tx = __ldg(&toff[0]);
    const float ty = __ldg(&toff[1]);
    const float tz = __ldg(&toff[2]);

    // 4 rays = 12 floats = 3 float4 per array; front-batched LDG.128 x6
    float4 p0 = P4[3 * i + 0], p1 = P4[3 * i + 1], p2 = P4[3 * i + 2];
    float4 v0 = V4[3 * i + 0], v1 = V4[3 * i + 1], v2 = V4[3 * i + 2];

    float Pf[12] = {p0.x, p0.y, p0.z, p0.w, p1.x, p1.y, p1.z, p1.w,
                    p2.x, p2.y, p2.z, p2.w};
    float Vf[12] = {v0.x, v0.y, v0.z, v0.w, v1.x, v1.y, v1.z, v1.w,
                    v2.x, v2.y, v2.z, v2.w};

    float Of[12], Tf[12], Wf[4];
#pragma unroll
    for (int j = 0; j < 4; j++) {
        trace_one(Pf[3*j], Pf[3*j+1], Pf[3*j+2],
                  Vf[3*j], Vf[3*j+1], Vf[3*j+2],
                  tx, ty, tz,
                  Of[3*j], Of[3*j+1], Of[3*j+2],
                  Tf[3*j], Tf[3*j+1], Tf[3*j+2],
                  Wf[j]);
    }

    pt4[3*i+0] = make_float4(Of[0], Of[1], Of[2],  Of[3]);
    pt4[3*i+1] = make_float4(Of[4], Of[5], Of[6],  Of[7]);
    pt4[3*i+2] = make_float4(Of[8], Of[9], Of[10], Of[11]);
    T4[3*i+0]  = make_float4(Tf[0], Tf[1], Tf[2],  Tf[3]);
    T4[3*i+1]  = make_float4(Tf[4], Tf[5], Tf[6],  Tf[7]);
    T4[3*i+2]  = make_float4(Tf[8], Tf[9], Tf[10], Tf[11]);
    vld4[i]    = make_float4(Wf[0], Wf[1], Wf[2],  Wf[3]);
}

// Scalar tail for N % 4 != 0 (not expected for N = 8388608, but safe).
__global__ void optical_tail_kernel(const float* __restrict__ P,
                                    const float* __restrict__ V,
                                    const float* __restrict__ toff,
                                    float* __restrict__ pt,
                                    float* __restrict__ T,
                                    float* __restrict__ vld,
                                    int start, int n)
{
    int r = start + blockIdx.x * blockDim.x + threadIdx.x;
    if (r >= n) return;
    float tx = toff[0], ty = toff[1], tz = toff[2];
    float ox, oy, oz, Tx, Ty, Tz, w;
    trace_one(P[3*r], P[3*r+1], P[3*r+2],
              V[3*r], V[3*r+1], V[3*r+2],
              tx, ty, tz, ox, oy, oz, Tx, Ty, Tz, w);
    pt[3*r] = ox; pt[3*r+1] = oy; pt[3*r+2] = oz;
    T[3*r]  = Tx; T[3*r+1]  = Ty; T[3*r+2]  = Tz;
    vld[r]  = w;
}

extern "C" void kernel_launch(void* const* d_in, const int* in_sizes, int n_in,
                              void* d_out, int out_size)
{
    const float* P    = (const float*)d_in[0];   // [N,3]
    const float* V    = (const float*)d_in[1];   // [N,3]
    const float* toff = (const float*)d_in[2];   // [3]

    const int N = in_sizes[0] / 3;

    float* out = (float*)d_out;            // layout: pt[3N] | T[3N] | valid[N]
    float* pt  = out;
    float* T   = out + (size_t)3 * N;
    float* vld = out + (size_t)6 * N;

    const int nq  = N / 4;                 // quads handled by the vector kernel
    const int rem = N - nq * 4;

    if (nq > 0) {
        int threads = 256;
        int blocks  = (nq + threads - 1) / threads;
        optical_quad_kernel<<<blocks, threads>>>(
            (const float4*)P, (const float4*)V, toff,
            (float4*)pt, (float4*)T, (float4*)vld, nq);
    }
    if (rem > 0) {
        optical_tail_kernel<<<1, 128>>>(P, V, toff, pt, T, vld, nq * 4, N);
    }
}